// round 2
// baseline (speedup 1.0000x reference)
#include <cuda_runtime.h>
#include <cuda_fp16.h>
#include <cstdint>
#include <math.h>

// Problem constants
#define PP    16
#define EE    512
#define HH    512
#define NTOT  8192

// Tiling
#define MT       128   // rows per CTA
#define NCHW     128   // N chunk width
#define THREADS  256

#define ASTRIDE  1040  // bytes per A row: 512 halves + 16B pad (bank-conflict-free ldmatrix)
#define BSTRIDE  144   // bytes per B row: 64 halves + 16B pad

#define SA     0
#define SB     (MT * ASTRIDE)            // 133120
#define SBSZ   (NCHW * BSTRIDE)          // 18432
#define SBIAS  (SB + 2 * SBSZ)           // 169984
#define SRED   (SBIAS + 3 * 2048)        // 176128
#define SMEM_BYTES (SRED + MT * 2 * 4)   // 177152

// Static device scratch (no runtime allocation)
__device__ __align__(16) __half g_e[(size_t)NTOT * EE];        // e, fp16
__device__ __align__(16) __half g_w0t[(size_t)PP * HH * EE];   // W0^T [p][h_out][e]
__device__ __align__(16) __half g_w1t[(size_t)PP * HH * HH];   // W1^T [p][h_out][h_in]
__device__ __align__(16) __half g_h[(size_t)PP * NTOT * HH];   // hidden scratch

// ---------------------------------------------------------------------------
// Base-ISA PTX helpers (no sm_103a features!)
// ---------------------------------------------------------------------------
__device__ __forceinline__ uint32_t smem_u32(const void* p) {
    uint32_t a;
    asm("{ .reg .u64 t; cvta.to.shared.u64 t, %1; cvt.u32.u64 %0, t; }"
        : "=r"(a) : "l"(p));
    return a;
}
__device__ __forceinline__ void cp16(uint32_t dst, const void* src) {
    asm volatile("cp.async.cg.shared.global [%0], [%1], 16;" :: "r"(dst), "l"(src));
}
__device__ __forceinline__ void cp_commit() { asm volatile("cp.async.commit_group;" ::: "memory"); }
template <int N>
__device__ __forceinline__ void cp_wait() { asm volatile("cp.async.wait_group %0;" :: "n"(N) : "memory"); }

__device__ __forceinline__ void ldm4(uint32_t* r, uint32_t a) {
    asm volatile("ldmatrix.sync.aligned.m8n8.x4.shared.b16 {%0,%1,%2,%3}, [%4];"
                 : "=r"(r[0]), "=r"(r[1]), "=r"(r[2]), "=r"(r[3]) : "r"(a));
}
__device__ __forceinline__ void mma16816(float* c, const uint32_t* a, const uint32_t* b) {
    asm volatile(
        "mma.sync.aligned.m16n8k16.row.col.f32.f16.f16.f32 "
        "{%0,%1,%2,%3}, {%4,%5,%6,%7}, {%8,%9}, {%0,%1,%2,%3};"
        : "+f"(c[0]), "+f"(c[1]), "+f"(c[2]), "+f"(c[3])
        : "r"(a[0]), "r"(a[1]), "r"(a[2]), "r"(a[3]), "r"(b[0]), "r"(b[1]));
}

// ---------------------------------------------------------------------------
// Pre-pass kernels: fp32 -> fp16 convert (+ transpose for weights)
// ---------------------------------------------------------------------------
__global__ void conv_e_kernel(const float* __restrict__ e) {
    int i = blockIdx.x * blockDim.x + threadIdx.x;   // handles 4 floats
    float4 v = ((const float4*)e)[i];
    __half2 a = __floats2half2_rn(v.x, v.y);
    __half2 b = __floats2half2_rn(v.z, v.w);
    uint2 pk;
    pk.x = *(uint32_t*)&a;
    pk.y = *(uint32_t*)&b;
    ((uint2*)g_e)[i] = pk;
}

// W [P, K=512 (in), C=512 (out)] -> Wt [P, C, K] fp16 (tiled transpose)
__global__ void conv_wt_kernel(const float* __restrict__ W, int which) {
    __shared__ float tile[32][33];
    __half* Wt = which ? g_w1t : g_w0t;
    int p = blockIdx.z;
    const float* w = W + (size_t)p * 512 * 512;
    __half* wt = Wt + (size_t)p * 512 * 512;
    int c0 = blockIdx.x * 32, r0 = blockIdx.y * 32;
    for (int j = threadIdx.y; j < 32; j += 8)
        tile[j][threadIdx.x] = w[(size_t)(r0 + j) * 512 + c0 + threadIdx.x];
    __syncthreads();
    for (int j = threadIdx.y; j < 32; j += 8)
        wt[(size_t)(c0 + j) * 512 + r0 + threadIdx.x] = __float2half(tile[threadIdx.x][j]);
}

// ---------------------------------------------------------------------------
// Fused MLP kernel (HMMA mma.sync)
// ---------------------------------------------------------------------------
__global__ void __launch_bounds__(THREADS, 1)
mlp_fused(const float* __restrict__ b0, const float* __restrict__ b1,
          const float* __restrict__ W2, const float* __restrict__ b2,
          float* __restrict__ out) {
    extern __shared__ char smem[];
    uint32_t sb = smem_u32(smem);
    int tid = threadIdx.x;
    int lane = tid & 31, wid = tid >> 5;
    int wm = wid & 3;        // 0..3, 32 rows each
    int wn = wid >> 2;       // 0..1, 64 cols each
    int p = blockIdx.x >> 6; // 64 M-tiles per partition, consecutive -> L2 weight reuse
    int mt = blockIdx.x & 63;
    int m0 = mt * MT;

    float* b0s = (float*)(smem + SBIAS);
    float* b1s = (float*)(smem + SBIAS + 2048);
    float* w2s = (float*)(smem + SBIAS + 4096);
    for (int j = tid; j < 512; j += THREADS) {
        b0s[j] = b0[p * 512 + j];
        b1s[j] = b1[p * 512 + j];
        w2s[j] = W2[p * 512 + j];
    }

    // Load A = e tile [128 x 512 halves] into padded smem via cp.async
    for (int i = tid; i < MT * 64; i += THREADS) {   // 64 x 16B chunks per row
        int row = i >> 6, c = i & 63;
        cp16(sb + SA + row * ASTRIDE + c * 16, g_e + ((size_t)(m0 + row)) * EE + c * 8);
    }
    cp_commit();
    cp_wait<0>();
    __syncthreads();

    // ldmatrix lane-address components
    // A .x4 matrices: (m0,k0),(m0+8,k0),(m0,k8),(m0+8,k8)
    int selA = lane >> 3;
    int a_row  = (selA & 1) * 8 + (lane & 7);
    int a_koff = (selA >> 1) * 8;
    // B .x4 matrices: (n0,k0),(n0,k8),(n8,k0),(n8,k8) -> regs b0f0,b1f0,b0f1,b1f1
    int b_row  = (lane >> 4) * 8 + (lane & 7);
    int b_koff = ((lane >> 3) & 1) * 8;

    float pacc[2][2] = {{0.f, 0.f}, {0.f, 0.f}};

#pragma unroll 1
    for (int layer = 0; layer < 2; layer++) {
        const __half* Wt = (layer == 0) ? (g_w0t + (size_t)p * HH * EE)
                                        : (g_w1t + (size_t)p * HH * HH);
        float* bias = (layer == 0) ? b0s : b1s;

#pragma unroll 1
        for (int nch = 0; nch < 4; nch++) {
            // preload kc = 0 into buf 0
            for (int i = tid; i < NCHW * 8; i += THREADS) {
                int r = i >> 3, c = i & 7;
                cp16(sb + SB + r * BSTRIDE + c * 16,
                     Wt + ((size_t)(nch * 128 + r)) * 512 + c * 8);
            }
            cp_commit();

            float acc[2][8][4];
#pragma unroll
            for (int mf = 0; mf < 2; mf++)
#pragma unroll
                for (int nf = 0; nf < 8; nf++)
#pragma unroll
                    for (int u = 0; u < 4; u++) acc[mf][nf][u] = 0.f;

#pragma unroll 1
            for (int kc = 0; kc < 8; kc++) {
                int buf = kc & 1;
                if (kc < 7) {
                    int nb = buf ^ 1;
                    for (int i = tid; i < NCHW * 8; i += THREADS) {
                        int r = i >> 3, c = i & 7;
                        cp16(sb + SB + nb * SBSZ + r * BSTRIDE + c * 16,
                             Wt + ((size_t)(nch * 128 + r)) * 512 + (kc + 1) * 64 + c * 8);
                    }
                    cp_commit();
                    cp_wait<1>();
                } else {
                    cp_wait<0>();
                }
                __syncthreads();

                uint32_t bbase = sb + SB + buf * SBSZ;
#pragma unroll
                for (int ks = 0; ks < 4; ks++) {
                    int kk = kc * 64 + ks * 16;    // k index in halves (A buffer)
                    uint32_t aR[2][4];
#pragma unroll
                    for (int mf = 0; mf < 2; mf++) {
                        int row = wm * 32 + mf * 16 + a_row;
                        ldm4(aR[mf], sb + SA + row * ASTRIDE + (kk + a_koff) * 2);
                    }
                    uint32_t bR[4][4];
#pragma unroll
                    for (int nf2 = 0; nf2 < 4; nf2++) {
                        int n = wn * 64 + nf2 * 16 + b_row;
                        ldm4(bR[nf2], bbase + n * BSTRIDE + (ks * 16 + b_koff) * 2);
                    }
#pragma unroll
                    for (int mf = 0; mf < 2; mf++)
#pragma unroll
                        for (int nf = 0; nf < 8; nf++)
                            mma16816(acc[mf][nf], aR[mf], &bR[nf >> 1][(nf & 1) * 2]);
                }
                __syncthreads();
            }

            // Epilogue for this N-chunk
            if (layer == 0) {
#pragma unroll
                for (int mf = 0; mf < 2; mf++) {
                    size_t r0 = (size_t)(p * NTOT) + m0 + wm * 32 + mf * 16 + (lane >> 2);
#pragma unroll
                    for (int nf = 0; nf < 8; nf++) {
                        int col = nch * 128 + wn * 64 + nf * 8 + (lane & 3) * 2;
                        float* c4 = acc[mf][nf];
                        __half2 h0 = __floats2half2_rn(fmaxf(c4[0] + bias[col], 0.f),
                                                       fmaxf(c4[1] + bias[col + 1], 0.f));
                        __half2 h1 = __floats2half2_rn(fmaxf(c4[2] + bias[col], 0.f),
                                                       fmaxf(c4[3] + bias[col + 1], 0.f));
                        *(__half2*)(g_h + r0 * HH + col) = h0;
                        *(__half2*)(g_h + (r0 + 8) * HH + col) = h1;
                    }
                }
            } else {
#pragma unroll
                for (int mf = 0; mf < 2; mf++) {
#pragma unroll
                    for (int nf = 0; nf < 8; nf++) {
                        int col = nch * 128 + wn * 64 + nf * 8 + (lane & 3) * 2;
                        float* c4 = acc[mf][nf];
                        float w0v = w2s[col], w1v = w2s[col + 1];
                        pacc[mf][0] = fmaf(fmaxf(c4[0] + bias[col], 0.f), w0v,
                                      fmaf(fmaxf(c4[1] + bias[col + 1], 0.f), w1v, pacc[mf][0]));
                        pacc[mf][1] = fmaf(fmaxf(c4[2] + bias[col], 0.f), w0v,
                                      fmaf(fmaxf(c4[3] + bias[col + 1], 0.f), w1v, pacc[mf][1]));
                    }
                }
            }
        }

        if (layer == 0) {
            __syncthreads();   // all g_h writes of this CTA visible
            // Reload H tile into the A buffer
            for (int i = tid; i < MT * 64; i += THREADS) {
                int row = i >> 6, c = i & 63;
                cp16(sb + SA + row * ASTRIDE + c * 16,
                     g_h + ((size_t)(p * NTOT) + m0 + row) * HH + c * 8);
            }
            cp_commit();
            cp_wait<0>();
            __syncthreads();
        }
    }

    // Final reduction: sum pacc over lanes sharing a row, then across warp_n
    float* red = (float*)(smem + SRED);
#pragma unroll
    for (int mf = 0; mf < 2; mf++)
#pragma unroll
        for (int rp = 0; rp < 2; rp++) {
            float v = pacc[mf][rp];
            v += __shfl_xor_sync(0xffffffffu, v, 1);
            v += __shfl_xor_sync(0xffffffffu, v, 2);
            if ((lane & 3) == 0) {
                int row = wm * 32 + mf * 16 + rp * 8 + (lane >> 2);
                red[row * 2 + wn] = v;
            }
        }
    __syncthreads();
    if (tid < MT) {
        float z = red[tid * 2] + red[tid * 2 + 1] + b2[p];
        out[((size_t)(m0 + tid)) * PP + p] = 1.f / (1.f + __expf(-z));
    }
}

// ---------------------------------------------------------------------------
// Launch
// ---------------------------------------------------------------------------
extern "C" void kernel_launch(void* const* d_in, const int* in_sizes, int n_in,
                              void* d_out, int out_size) {
    const float* e  = (const float*)d_in[0];
    const float* W0 = (const float*)d_in[1];
    const float* b0 = (const float*)d_in[2];
    const float* W1 = (const float*)d_in[3];
    const float* b1 = (const float*)d_in[4];
    const float* W2 = (const float*)d_in[5];
    const float* b2 = (const float*)d_in[6];
    float* out = (float*)d_out;

    cudaFuncSetAttribute(mlp_fused, cudaFuncAttributeMaxDynamicSharedMemorySize, SMEM_BYTES);

    conv_e_kernel<<<(NTOT * EE / 4) / 256, 256>>>(e);
    conv_wt_kernel<<<dim3(16, 16, PP), dim3(32, 8)>>>(W0, 0);
    conv_wt_kernel<<<dim3(16, 16, PP), dim3(32, 8)>>>(W1, 1);
    mlp_fused<<<PP * (NTOT / MT), THREADS, SMEM_BYTES>>>(b0, b1, W2, b2, out);
}